// round 8
// baseline (speedup 1.0000x reference)
#include <cuda_runtime.h>

#define HH 256
#define WW 256
#define BB 8
#define IMG_PIX (HH*WW)          // 65536
#define NPIX (BB*IMG_PIX)        // 524288

static __device__ float  g_gray[2][NPIX];
static __device__ float4 g_cst[NPIX];     // {dx, dy, rho_c+EPS, th}
static __device__ float2 g_u[2][NPIX];
static __device__ float4 g_p[2][NPIX];
static __device__ int    g_mn, g_mx;

__constant__ float GW[25] = {
    0.000874f, 0.006976f, 0.01386f,  0.006976f, 0.000874f,
    0.006976f, 0.0557f,   0.110656f, 0.0557f,   0.006976f,
    0.01386f,  0.110656f, 0.219833f, 0.110656f, 0.01386f,
    0.006976f, 0.0557f,   0.110656f, 0.0557f,   0.006976f,
    0.000874f, 0.006976f, 0.01386f,  0.006976f, 0.000874f
};

#define L_T    0.045f
#define THETA  0.3f
#define TAUT   0.8333333333333334f
#define EPSV   1e-12f

__device__ __forceinline__ float rsqrt_approx(float x){
    float y; asm("rsqrt.approx.f32 %0, %1;" : "=f"(y) : "f"(x)); return y;
}
__device__ __forceinline__ float rcp_approx(float x){
    float y; asm("rcp.approx.f32 %0, %1;" : "=f"(y) : "f"(x)); return y;
}

__global__ void k_init(){ g_mn = 0x7f7fffff; g_mx = 0; }

// gray conversion + global min/max reduction over BOTH images
__global__ __launch_bounds__(256) void k_gray(const float* __restrict__ x1,
                                              const float* __restrict__ x2)
{
    int idx = blockIdx.x*256 + threadIdx.x;     // < NPIX
    int b   = idx >> 16;
    int pix = idx & 65535;
    int o   = b*3*IMG_PIX + pix;
    float g1 = 0.114f*x1[o] + 0.587f*x1[o+IMG_PIX] + 0.299f*x1[o+2*IMG_PIX];
    float g2 = 0.114f*x2[o] + 0.587f*x2[o+IMG_PIX] + 0.299f*x2[o+2*IMG_PIX];
    g_gray[0][idx] = g1;
    g_gray[1][idx] = g2;
    float mn = fminf(g1, g2), mx = fmaxf(g1, g2);
    #pragma unroll
    for (int off = 16; off; off >>= 1){
        mn = fminf(mn, __shfl_xor_sync(0xffffffffu, mn, off));
        mx = fmaxf(mx, __shfl_xor_sync(0xffffffffu, mx, off));
    }
    __shared__ float smn[8], smx[8];
    int lane = threadIdx.x & 31, w = threadIdx.x >> 5;
    if (!lane){ smn[w] = mn; smx[w] = mx; }
    __syncthreads();
    if (threadIdx.x == 0){
        #pragma unroll
        for (int i = 1; i < 8; i++){ mn = fminf(mn, smn[i]); mx = fmaxf(mx, smx[i]); }
        atomicMin(&g_mn, __float_as_int(mn));   // values >= 0: int order == float order
        atomicMax(&g_mx, __float_as_int(mx));
    }
}

// Fused: normalize + 5x5 gaussian (both images) + centered grad of smooth(s2)
// + per-pixel constants + zero-init of u/p.
__global__ __launch_bounds__(256) void k_fprep()
{
    __shared__ float sg1[38*38];
    __shared__ float sg2[38*38];
    __shared__ float ss2[34*34];

    const int b = blockIdx.z;
    const int tx0 = blockIdx.x*32, ty0 = blockIdx.y*32;
    const float mn = __int_as_float(g_mn);
    const float mx = __int_as_float(g_mx);
    const float scale = 255.0f / (mx - mn);
    const float* __restrict__ G1 = g_gray[0] + b*IMG_PIX;
    const float* __restrict__ G2 = g_gray[1] + b*IMG_PIX;
    const int tid = threadIdx.x;

    for (int idx = tid; idx < 38*38; idx += 256){
        int li = idx/38, lj = idx - li*38;
        int gi = ty0 + li - 3, gj = tx0 + lj - 3;
        float v1 = 0.f, v2 = 0.f;
        if (((unsigned)gi < HH) && ((unsigned)gj < WW)){
            int g = gi*WW + gj;
            v1 = (G1[g] - mn)*scale;
            v2 = (G2[g] - mn)*scale;
        }
        sg1[idx] = v1; sg2[idx] = v2;
    }
    __syncthreads();

    for (int idx = tid; idx < 34*34; idx += 256){
        int li = idx/34, lj = idx - li*34;
        float acc = 0.f;
        #pragma unroll
        for (int a = 0; a < 5; a++)
            #pragma unroll
            for (int c = 0; c < 5; c++)
                acc += GW[a*5+c]*sg2[(li+a)*38 + lj + c];
        ss2[idx] = acc;
    }
    __syncthreads();

    const int lj = tid & 31, li0 = tid >> 5;
    #pragma unroll
    for (int r = 0; r < 4; r++){
        int li = li0 + r*8;                 // 0..31
        int gi = ty0 + li, gj = tx0 + lj;
        float s1 = 0.f;
        #pragma unroll
        for (int a = 0; a < 5; a++)
            #pragma unroll
            for (int c = 0; c < 5; c++)
                s1 += GW[a*5+c]*sg1[(li+1+a)*38 + lj+1 + c];
        float cen = ss2[(li+1)*34 + lj+1];
        int jr = min(gj+1, WW-1) - tx0 + 1;
        int jl = max(gj-1, 0)    - tx0 + 1;
        int id = min(gi+1, HH-1) - ty0 + 1;
        int iu = max(gi-1, 0)    - ty0 + 1;
        float dx = 0.5f*(ss2[(li+1)*34 + jr] - ss2[(li+1)*34 + jl]);
        float dy = 0.5f*(ss2[id*34 + lj+1]  - ss2[iu*34 + lj+1]);
        float grad = dx*dx + dy*dy + EPSV;
        int g = b*IMG_PIX + gi*WW + gj;
        g_cst[g]    = make_float4(dx, dy, cen - s1 + EPSV, L_T*grad);
        g_u[0][g]   = make_float2(0.f, 0.f);
        g_p[0][g]   = make_float4(0.f, 0.f, 0.f, 0.f);
    }
}

// u-update body. Valid only for in-image (gi,gj).
// Invariant: p11/p21 == 0 on the last image column and p12/p22 == 0 on the
// last image row (maintained by the p-pass boundary selects), so the
// divergence needs no right/bottom predicates; only up/left loads are guarded.
__device__ __forceinline__ float2 u_update(const float4* __restrict__ p_in,
                                           const float2* __restrict__ u_in,
                                           int g, int gi, int gj,
                                           float4& pc_out, float& rho_out)
{
    float4 c  = __ldg(&g_cst[g]);
    float2 u  = __ldg(&u_in[g]);
    float4 pc = __ldg(&p_in[g]);
    float4 pl = (gj > 0) ? __ldg(&p_in[g-1])  : make_float4(0.f,0.f,0.f,0.f);
    float4 pu = (gi > 0) ? __ldg(&p_in[g-WW]) : make_float4(0.f,0.f,0.f,0.f);
    pc_out = pc;
    float rho = c.z + c.x*u.x + c.y*u.y;
    rho_out = rho;
    float ig = L_T * rcp_approx(c.w);      // == 1/grad in effect
    float coef = (rho < -c.w) ? L_T : ((rho > c.w) ? -L_T : -rho*ig);
    float d1 = pc.x - pl.x + pc.y - pu.y;
    float d2 = pc.z - pl.z + pc.w - pu.w;
    float2 un;
    un.x = fmaf(coef, c.x, u.x) + THETA*d1;
    un.y = fmaf(coef, c.y, u.y) + THETA*d2;
    return un;
}

// One TV-L1 iteration. 16x32 tile, 256 threads, 2 pixels/thread.
// 1024 blocks x 8 warps -> ~56 warps/SM resident (vs 28 last round).
__global__ __launch_bounds__(256) void k_iter(int s, int last, float* __restrict__ out)
{
    __shared__ float2 su[17*33];

    const int tx = threadIdx.x & 31, ty = threadIdx.x >> 5;   // ty in [0,8)
    const int tx0 = blockIdx.x*32, ty0 = blockIdx.y*16, b = blockIdx.z;
    const int base = b*IMG_PIX;
    const float4* __restrict__ p_in = g_p[s];
    const float2* __restrict__ u_in = g_u[s];
    float4* __restrict__ p_out = g_p[s^1];
    float2* __restrict__ u_out = g_u[s^1];

    float4 pc_r[2];

    // ---- u-pass: own 2 pixels (rows ty and ty+8) ----
    #pragma unroll
    for (int r = 0; r < 2; r++){
        int li = r*8 + ty;
        int gi = ty0 + li, gj = tx0 + tx;
        int g = base + gi*WW + gj;
        float rho;
        float2 un = u_update(p_in, u_in, g, gi, gj, pc_r[r], rho);
        su[li*33 + tx] = un;
        if (last) out[b*3*IMG_PIX + 2*IMG_PIX + gi*WW + gj] = rho;
    }
    // ---- u-pass halo: bottom row (warp 0), right column (warp 1) ----
    if (ty == 0){
        int gi = ty0 + 16, gj = tx0 + tx;
        if (gi < HH){
            int g = base + gi*WW + gj;
            float4 dummy; float rho;
            su[16*33 + tx] = u_update(p_in, u_in, g, gi, gj, dummy, rho);
        }
    } else if (ty == 1 && tx < 16){
        int gi = ty0 + tx, gj = tx0 + 32;
        if (gj < WW){
            int g = base + gi*WW + gj;
            float4 dummy; float rho;
            su[tx*33 + 32] = u_update(p_in, u_in, g, gi, gj, dummy, rho);
        }
    }
    __syncthreads();

    // ---- p-pass: own 2 pixels ----
    #pragma unroll
    for (int r = 0; r < 2; r++){
        int li = r*8 + ty;
        int gi = ty0 + li, gj = tx0 + tx;
        int g = base + gi*WW + gj;
        float2 uc = su[li*33 + tx];
        float2 ur = su[li*33 + tx + 1];
        float2 ud = su[(li+1)*33 + tx];
        bool bx = (gj == WW-1), by = (gi == HH-1);
        float u1x = bx ? 0.f : ur.x - uc.x;
        float u2x = bx ? 0.f : ur.y - uc.y;
        float u1y = by ? 0.f : ud.x - uc.x;
        float u2y = by ? 0.f : ud.y - uc.y;
        float s1 = u1x*u1x + u1y*u1y + EPSV;
        float s2 = u2x*u2x + u2y*u2y + EPSV;
        float ng1 = 1.f + TAUT*(s1*rsqrt_approx(s1));
        float ng2 = 1.f + TAUT*(s2*rsqrt_approx(s2));
        float r1 = rcp_approx(ng1), r2 = rcp_approx(ng2);
        float4 p = pc_r[r];
        if (last){
            int ob = b*3*IMG_PIX + gi*WW + gj;
            out[ob]           = uc.x;
            out[ob + IMG_PIX] = uc.y;
        } else {
            p_out[g] = make_float4((p.x + TAUT*u1x)*r1, (p.y + TAUT*u1y)*r1,
                                   (p.z + TAUT*u2x)*r2, (p.w + TAUT*u2y)*r2);
            u_out[g] = uc;
        }
    }
}

extern "C" void kernel_launch(void* const* d_in, const int* in_sizes, int n_in,
                              void* d_out, int out_size)
{
    const float* x1 = (const float*)d_in[0];
    const float* x2 = (const float*)d_in[1];
    float* out = (float*)d_out;

    k_init<<<1, 1>>>();
    k_gray<<<NPIX/256, 256>>>(x1, x2);
    dim3 gP(8, 8, 8);
    k_fprep<<<gP, 256>>>();
    dim3 gI(8, 16, 8);
    for (int it = 0; it < 30; ++it)
        k_iter<<<gI, 256>>>(it & 1, it == 29, out);
}